// round 1
// baseline (speedup 1.0000x reference)
#include <cuda_runtime.h>
#include <cuda_fp16.h>
#include <cstdint>

#define NTOK   49
#define NHD    8
#define HDIM   32
#define DMODEL 256
#define NBATCH 4096
#define NWIN   64

// fp16 scratch for Q, K, V in [B][NH][49][32] layout. ~98MB each. Static
// __device__ arrays (no allocation allowed in kernel_launch).
__device__ __half g_q[(size_t)NBATCH * NHD * NTOK * HDIM];
__device__ __half g_k[(size_t)NBATCH * NHD * NTOK * HDIM];
__device__ __half g_v[(size_t)NBATCH * NHD * NTOK * HDIM];

__device__ __forceinline__ void mma16816(float c[4],
                                         uint32_t a0, uint32_t a1, uint32_t a2, uint32_t a3,
                                         uint32_t b0, uint32_t b1) {
    asm volatile(
        "mma.sync.aligned.m16n8k16.row.col.f32.f16.f16.f32 "
        "{%0,%1,%2,%3}, {%4,%5,%6,%7}, {%8,%9}, {%0,%1,%2,%3};"
        : "+f"(c[0]), "+f"(c[1]), "+f"(c[2]), "+f"(c[3])
        : "r"(a0), "r"(a1), "r"(a2), "r"(a3), "r"(b0), "r"(b1));
}

// ---------------------------------------------------------------------------
// Kernel A: fused QKV projection GEMM.
// C[M=200704, 768] = X[M,256] @ [Wq|Wk|Wv] + bias, scattered to g_q/g_k/g_v
// as fp16 in [B][NH][49][32] layout. Q additionally scaled by 1/sqrt(32).
// Tiles: BM=128, BN=128, BK=32. 256 threads = 8 warps (2m x 4n), warp tile
// 64x32 = 4 m16-tiles x 4 n8-tiles.
// grid = (6, 1568): x (n-block) fastest so 6 CTAs sharing an A tile co-run.
// ---------------------------------------------------------------------------
__global__ __launch_bounds__(256) void qkv_kernel(
    const float* __restrict__ X,
    const float* __restrict__ wq, const float* __restrict__ bq,
    const float* __restrict__ wk, const float* __restrict__ bk,
    const float* __restrict__ wv, const float* __restrict__ bv)
{
    __shared__ __half As[128][40];   // 40-half stride -> conflict-free frags
    __shared__ __half Bs[128][40];   // stores W tile transposed: Bs[n][k]

    const int bx  = blockIdx.x;          // 0..5
    const int by  = blockIdx.y;          // 0..1567
    const int tid = threadIdx.x;
    const int warp = tid >> 5, lane = tid & 31;
    const int wm = warp & 1, wn = warp >> 1;
    const int g = lane >> 2, tig = lane & 3;

    const int mat   = bx >> 1;               // 0=Q 1=K 2=V
    const int ncol0 = (bx & 1) * 128;        // column offset inside weight
    const float* W    = (mat == 0) ? wq : (mat == 1) ? wk : wv;
    const float* bias = (mat == 0) ? bq : (mat == 1) ? bk : bv;

    float acc[4][4][4];
#pragma unroll
    for (int mt = 0; mt < 4; mt++)
#pragma unroll
        for (int nt = 0; nt < 4; nt++)
#pragma unroll
            for (int e = 0; e < 4; e++) acc[mt][nt][e] = 0.f;

    for (int kp = 0; kp < 8; kp++) {
        // Load A tile: 128 rows x 32 cols fp32 -> half
#pragma unroll
        for (int i = 0; i < 4; i++) {
            int idx = tid + i * 256;
            int r = idx >> 3, c4 = (idx & 7) * 4;
            float4 v4 = *(const float4*)(X + (size_t)(by * 128 + r) * DMODEL + kp * 32 + c4);
            As[r][c4 + 0] = __float2half_rn(v4.x);
            As[r][c4 + 1] = __float2half_rn(v4.y);
            As[r][c4 + 2] = __float2half_rn(v4.z);
            As[r][c4 + 3] = __float2half_rn(v4.w);
        }
        // Load B tile transposed: Bs[n][k] = W[kp*32+k][ncol0+n]
#pragma unroll
        for (int i = 0; i < 16; i++) {
            int idx = tid + i * 256;
            int kk = idx >> 7, nn = idx & 127;
            Bs[nn][kk] = __float2half_rn(W[(size_t)(kp * 32 + kk) * DMODEL + ncol0 + nn]);
        }
        __syncthreads();

#pragma unroll
        for (int ks = 0; ks < 2; ks++) {
            uint32_t bf[4][2];
#pragma unroll
            for (int nt = 0; nt < 4; nt++) {
                int n = wn * 32 + nt * 8 + g;
                bf[nt][0] = *(const uint32_t*)&Bs[n][ks * 16 + 2 * tig];
                bf[nt][1] = *(const uint32_t*)&Bs[n][ks * 16 + 2 * tig + 8];
            }
#pragma unroll
            for (int mt = 0; mt < 4; mt++) {
                int r0 = wm * 64 + mt * 16;
                uint32_t a0 = *(const uint32_t*)&As[r0 + g][ks * 16 + 2 * tig];
                uint32_t a1 = *(const uint32_t*)&As[r0 + g + 8][ks * 16 + 2 * tig];
                uint32_t a2 = *(const uint32_t*)&As[r0 + g][ks * 16 + 2 * tig + 8];
                uint32_t a3 = *(const uint32_t*)&As[r0 + g + 8][ks * 16 + 2 * tig + 8];
#pragma unroll
                for (int nt = 0; nt < 4; nt++)
                    mma16816(acc[mt][nt], a0, a1, a2, a3, bf[nt][0], bf[nt][1]);
            }
        }
        __syncthreads();
    }

    // Epilogue: add bias, scale Q by 1/sqrt(32), scatter as half2
    __half* outp = (mat == 0) ? g_q : (mat == 1) ? g_k : g_v;
    const float scale = (mat == 0) ? 0.17677669529663687f : 1.0f;
#pragma unroll
    for (int mt = 0; mt < 4; mt++) {
#pragma unroll
        for (int hf = 0; hf < 2; hf++) {
            int m = by * 128 + wm * 64 + mt * 16 + g + hf * 8;   // < 200704 always
            int b = m / NTOK, n = m - b * NTOK;
#pragma unroll
            for (int nt = 0; nt < 4; nt++) {
                int c = ncol0 + wn * 32 + nt * 8 + 2 * tig;      // 0..255
                int h = c >> 5, d = c & 31;                      // d even
                float v0 = (acc[mt][nt][hf * 2 + 0] + bias[c]) * scale;
                float v1 = (acc[mt][nt][hf * 2 + 1] + bias[c + 1]) * scale;
                *(__half2*)(outp + ((((size_t)b * NHD + h) * NTOK + n) * HDIM + d)) =
                    __floats2half2_rn(v0, v1);
            }
        }
    }
}

// ---------------------------------------------------------------------------
// Kernel B: windowed attention. One CTA per (b, h). 4 warps, each owning one
// m16 row tile (rows padded 49->64). Scores 64x56 (keys padded 49->56),
// analytic relative-position bias + mask add, warp-shuffle softmax,
// P staged to smem as fp16, PV mma, fp32 output.
// ---------------------------------------------------------------------------
__device__ __forceinline__ int relidx(int i, int j) {
    int ih = i / 7, iw = i - ih * 7;
    int jh = j / 7, jw = j - jh * 7;
    return (ih - jh + 6) * 13 + (iw - jw + 6);
}

__global__ __launch_bounds__(128) void attn_kernel(
    const float* __restrict__ mask,     // [64,49,49]
    const float* __restrict__ table,    // [169,8]
    float* __restrict__ out)            // [4096,49,256]
{
    const int b = blockIdx.x;
    const int h = blockIdx.y;
    const int w = b & (NWIN - 1);

    __shared__ __half Qs[64][40];
    __shared__ __half Ks[56][40];
    __shared__ __half VsT[32][72];      // VsT[d][j]
    __shared__ __half Ps[64][72];

    const int tid = threadIdx.x;
    const int warp = tid >> 5, lane = tid & 31;
    const int g = lane >> 2, tig = lane & 3;

    const __half* qp = g_q + ((size_t)b * NHD + h) * (NTOK * HDIM);
    const __half* kp = g_k + ((size_t)b * NHD + h) * (NTOK * HDIM);
    const __half* vp = g_v + ((size_t)b * NHD + h) * (NTOK * HDIM);
    const __half2* qp2 = (const __half2*)qp;
    const __half2* kp2 = (const __half2*)kp;

    const __half2 zero2 = __float2half2_rn(0.f);

    // Q: 64 rows x 16 half2
    for (int idx = tid; idx < 64 * 16; idx += 128) {
        int r = idx >> 4, c2 = idx & 15;
        *(__half2*)&Qs[r][c2 * 2] = (r < NTOK) ? qp2[r * 16 + c2] : zero2;
    }
    // K: 56 rows x 16 half2
    for (int idx = tid; idx < 56 * 16; idx += 128) {
        int r = idx >> 4, c2 = idx & 15;
        *(__half2*)&Ks[r][c2 * 2] = (r < NTOK) ? kp2[r * 16 + c2] : zero2;
    }
    // V transposed + zero pad j in [48,64)
    for (int idx = tid; idx < 32 * 16; idx += 128) {
        int d = idx >> 4, j = 48 + (idx & 15);
        VsT[d][j] = __float2half(0.f);
    }
    for (int idx = tid; idx < NTOK * HDIM; idx += 128) {
        int j = idx >> 5, d = idx & 31;
        VsT[d][j] = vp[idx];
    }
    // zero P pad cols [56,64)
    for (int idx = tid; idx < 64 * 8; idx += 128) {
        int r = idx >> 3, c = 56 + (idx & 7);
        Ps[r][c] = __float2half(0.f);
    }
    __syncthreads();

    const int m0 = warp * 16;
    const int i0 = m0 + g, i1 = m0 + g + 8;

    // --- scores = Q @ K^T ---
    float sc[7][4];
#pragma unroll
    for (int nt = 0; nt < 7; nt++)
#pragma unroll
        for (int e = 0; e < 4; e++) sc[nt][e] = 0.f;

#pragma unroll
    for (int ks = 0; ks < 2; ks++) {
        uint32_t a0 = *(const uint32_t*)&Qs[i0][ks * 16 + 2 * tig];
        uint32_t a1 = *(const uint32_t*)&Qs[i1][ks * 16 + 2 * tig];
        uint32_t a2 = *(const uint32_t*)&Qs[i0][ks * 16 + 2 * tig + 8];
        uint32_t a3 = *(const uint32_t*)&Qs[i1][ks * 16 + 2 * tig + 8];
#pragma unroll
        for (int nt = 0; nt < 7; nt++) {
            int n = nt * 8 + g;
            uint32_t b0 = *(const uint32_t*)&Ks[n][ks * 16 + 2 * tig];
            uint32_t b1 = *(const uint32_t*)&Ks[n][ks * 16 + 2 * tig + 8];
            mma16816(sc[nt], a0, a1, a2, a3, b0, b1);
        }
    }

    // --- bias + mask, padding mask ---
#pragma unroll
    for (int nt = 0; nt < 7; nt++) {
#pragma unroll
        for (int e = 0; e < 4; e++) {
            int i = (e < 2) ? i0 : i1;
            int j = nt * 8 + 2 * tig + (e & 1);
            float v = sc[nt][e];
            if (j < NTOK) {
                if (i < NTOK)
                    v += table[relidx(i, j) * NHD + h] +
                         mask[((size_t)w * NTOK + i) * NTOK + j];
            } else {
                v = -1e30f;
            }
            sc[nt][e] = v;
        }
    }

    // --- softmax (rows i0 and i1, reduce across tig lanes 0..3) ---
    float mx0 = -1e30f, mx1 = -1e30f;
#pragma unroll
    for (int nt = 0; nt < 7; nt++) {
        mx0 = fmaxf(mx0, fmaxf(sc[nt][0], sc[nt][1]));
        mx1 = fmaxf(mx1, fmaxf(sc[nt][2], sc[nt][3]));
    }
    mx0 = fmaxf(mx0, __shfl_xor_sync(0xffffffffu, mx0, 1));
    mx0 = fmaxf(mx0, __shfl_xor_sync(0xffffffffu, mx0, 2));
    mx1 = fmaxf(mx1, __shfl_xor_sync(0xffffffffu, mx1, 1));
    mx1 = fmaxf(mx1, __shfl_xor_sync(0xffffffffu, mx1, 2));

    float s0 = 0.f, s1 = 0.f;
#pragma unroll
    for (int nt = 0; nt < 7; nt++) {
        sc[nt][0] = __expf(sc[nt][0] - mx0); s0 += sc[nt][0];
        sc[nt][1] = __expf(sc[nt][1] - mx0); s0 += sc[nt][1];
        sc[nt][2] = __expf(sc[nt][2] - mx1); s1 += sc[nt][2];
        sc[nt][3] = __expf(sc[nt][3] - mx1); s1 += sc[nt][3];
    }
    s0 += __shfl_xor_sync(0xffffffffu, s0, 1);
    s0 += __shfl_xor_sync(0xffffffffu, s0, 2);
    s1 += __shfl_xor_sync(0xffffffffu, s1, 1);
    s1 += __shfl_xor_sync(0xffffffffu, s1, 2);
    const float r0 = 1.f / s0, r1 = 1.f / s1;

    // stage P to smem (half)
#pragma unroll
    for (int nt = 0; nt < 7; nt++) {
        *(__half2*)&Ps[i0][nt * 8 + 2 * tig] = __floats2half2_rn(sc[nt][0], sc[nt][1]);
        *(__half2*)&Ps[i1][nt * 8 + 2 * tig] = __floats2half2_rn(sc[nt][2], sc[nt][3]);
    }
    __syncwarp();

    // --- ctx = P @ V ---
    float o[4][4];
#pragma unroll
    for (int nt = 0; nt < 4; nt++)
#pragma unroll
        for (int e = 0; e < 4; e++) o[nt][e] = 0.f;

#pragma unroll
    for (int kt = 0; kt < 4; kt++) {
        uint32_t a0 = *(const uint32_t*)&Ps[i0][kt * 16 + 2 * tig];
        uint32_t a1 = *(const uint32_t*)&Ps[i1][kt * 16 + 2 * tig];
        uint32_t a2 = *(const uint32_t*)&Ps[i0][kt * 16 + 2 * tig + 8];
        uint32_t a3 = *(const uint32_t*)&Ps[i1][kt * 16 + 2 * tig + 8];
#pragma unroll
        for (int nt = 0; nt < 4; nt++) {
            int n = nt * 8 + g;   // head-dim index
            uint32_t b0 = *(const uint32_t*)&VsT[n][kt * 16 + 2 * tig];
            uint32_t b1 = *(const uint32_t*)&VsT[n][kt * 16 + 2 * tig + 8];
            mma16816(o[nt], a0, a1, a2, a3, b0, b1);
        }
    }

    // --- write output [b, i, h*32 + d], fp32, normalized ---
#pragma unroll
    for (int nt = 0; nt < 4; nt++) {
        int d = nt * 8 + 2 * tig;
        if (i0 < NTOK) {
            float2 v = make_float2(o[nt][0] * r0, o[nt][1] * r0);
            *(float2*)(out + ((size_t)b * NTOK + i0) * DMODEL + h * HDIM + d) = v;
        }
        if (i1 < NTOK) {
            float2 v = make_float2(o[nt][2] * r1, o[nt][3] * r1);
            *(float2*)(out + ((size_t)b * NTOK + i1) * DMODEL + h * HDIM + d) = v;
        }
    }
}

extern "C" void kernel_launch(void* const* d_in, const int* in_sizes, int n_in,
                              void* d_out, int out_size)
{
    (void)in_sizes; (void)n_in; (void)out_size;
    const float* hidden = (const float*)d_in[0];
    const float* amask  = (const float*)d_in[1];
    const float* wq     = (const float*)d_in[2];
    const float* bq     = (const float*)d_in[3];
    const float* wk     = (const float*)d_in[4];
    const float* bk     = (const float*)d_in[5];
    const float* wv     = (const float*)d_in[6];
    const float* bv     = (const float*)d_in[7];
    const float* table  = (const float*)d_in[8];
    float* out = (float*)d_out;

    dim3 gridA(6, 1568);
    qkv_kernel<<<gridA, 256>>>(hidden, wq, bq, wk, bk, wv, bv);

    dim3 gridB(NBATCH, NHD);
    attn_kernel<<<gridB, 128>>>(amask, table, out);
}